// round 6
// baseline (speedup 1.0000x reference)
#include <cuda_runtime.h>
#include <cuda_bf16.h>
#include <cstdint>

#define Bsz  16
#define Cch  32
#define Himg 256
#define Wimg 256

#define TILE_H 16
#define TILE_W 32
#define HALO_W 34
#define NPIX   612            // 18 rows x 34 cols

#define THREADS 256

// smem byte offsets
#define A_OFF    0
#define WH_OFF   (NPIX * 128)            // 78336
#define WL_OFF   (WH_OFF + 9 * 2048)     // 96768
#define BIAS_OFF (WL_OFF + 9 * 2048)     // 115200
#define GATE_OFF (BIAS_OFF + 128)
#define SMEM_BYTES (GATE_OFF + 128)      // 115456

// h scratch: per pixel 32 bf16 = 16 uint32 (hi plane), + lo plane. 128 MB.
#define HPIX   (16u * 65536u)            // Bsz*Himg*Wimg
#define HLO32  (HPIX * 16u)              // uint32 offset of lo plane
__device__ uint32_t g_h[2ull * HPIX * 16u];

// ---------------- helpers ----------------
__device__ __forceinline__ uint32_t smem_u32(const void* p) {
    uint32_t a;
    asm("{ .reg .u64 t; cvta.to.shared.u64 t, %1; cvt.u32.u64 %0, t; }"
        : "=r"(a) : "l"(p));
    return a;
}
__device__ __forceinline__ void ldmx4(uint32_t* d, uint32_t a) {
    asm volatile("ldmatrix.sync.aligned.m8n8.x4.shared.b16 {%0,%1,%2,%3}, [%4];"
                 : "=r"(d[0]), "=r"(d[1]), "=r"(d[2]), "=r"(d[3]) : "r"(a));
}
__device__ __forceinline__ void ldmx4t(uint32_t* d, uint32_t a) {
    asm volatile("ldmatrix.sync.aligned.m8n8.x4.trans.shared.b16 {%0,%1,%2,%3}, [%4];"
                 : "=r"(d[0]), "=r"(d[1]), "=r"(d[2]), "=r"(d[3]) : "r"(a));
}
__device__ __forceinline__ void mma16816(float* c, const uint32_t* a, const uint32_t* b) {
    asm volatile("mma.sync.aligned.m16n8k16.row.col.f32.bf16.bf16.f32 "
                 "{%0,%1,%2,%3}, {%4,%5,%6,%7}, {%8,%9}, {%0,%1,%2,%3};"
                 : "+f"(c[0]), "+f"(c[1]), "+f"(c[2]), "+f"(c[3])
                 : "r"(a[0]), "r"(a[1]), "r"(a[2]), "r"(a[3]),
                   "r"(b[0]), "r"(b[1]));
}

// A-tile swizzled byte offset: pixel p, 16B-granule kc (0..7; hi=0..3, lo=4..7)
__device__ __forceinline__ uint32_t a_byte(int p, int kc) {
    return (uint32_t)(p * 128 + (((kc + p) & 7) << 4));
}
// W-tile swizzled byte offset within one tap region: k-row ci, n-block nb (0..3)
__device__ __forceinline__ uint32_t w_byte(int ci, int nb) {
    return (uint32_t)(ci * 64 + (((nb + ((ci >> 1) & 3)) & 3) << 4));
}

// ---------------- kernel ----------------
template <bool SECOND>
__global__ __launch_bounds__(THREADS)
void conv_hmma(const float* __restrict__ x,
               const float* __restrict__ w,
               const float* __restrict__ bias,
               const float* __restrict__ gate,
               float* __restrict__ out)
{
    extern __shared__ char sm[];
    const uint32_t smb = smem_u32(sm);
    const int tid = threadIdx.x;
    const int b  = blockIdx.z;
    const int y0 = blockIdx.y * TILE_H;
    const int x0 = blockIdx.x * TILE_W;

    // ---- weights -> [tap][ci][co] bf16 hi/lo, swizzled ----
    for (int i = tid; i < Cch * Cch * 9; i += THREADS) {
        int co = i / 288, rem = i - co * 288;
        int ci = rem / 9, tap = rem - ci * 9;
        float v = w[i];
        __nv_bfloat16 hh = __float2bfloat16(v);
        __nv_bfloat16 ll = __float2bfloat16(v - __bfloat162float(hh));
        uint32_t byte = tap * 2048 + w_byte(ci, co >> 3) + ((co & 7) << 1);
        *(__nv_bfloat16*)(sm + WH_OFF + byte) = hh;
        *(__nv_bfloat16*)(sm + WL_OFF + byte) = ll;
    }
    if (tid < 32) {
        ((float*)(sm + BIAS_OFF))[tid] = bias[tid];
        float g = gate[b * 32 + tid];
        ((float*)(sm + GATE_OFF))[tid] = (g > 0.0f) ? g : 0.0f;
    }

    // ---- A tile fill (channels-last, hi/lo, swizzled) ----
    if (!SECOND) {
        for (int i = tid; i < NPIX * 32; i += THREADS) {
            int ci = i / NPIX, p = i - ci * NPIX;
            int gy = y0 - 1 + p / HALO_W;
            int gx = x0 - 1 + p % HALO_W;
            float v = 0.0f;
            if ((unsigned)gy < (unsigned)Himg && (unsigned)gx < (unsigned)Wimg)
                v = x[(((size_t)b * Cch + ci) * Himg + gy) * Wimg + gx];
            __nv_bfloat16 hh = __float2bfloat16(v);
            __nv_bfloat16 ll = __float2bfloat16(v - __bfloat162float(hh));
            int sub = (ci & 7) << 1;
            *(__nv_bfloat16*)(sm + A_OFF + a_byte(p, ci >> 3) + sub)       = hh;
            *(__nv_bfloat16*)(sm + A_OFF + a_byte(p, 4 + (ci >> 3)) + sub) = ll;
        }
    } else {
        const uint4* gh4 = (const uint4*)g_h;
        for (int i = tid; i < NPIX * 4; i += THREADS) {
            int p = i >> 2, chunk = i & 3;
            int gy = y0 - 1 + p / HALO_W;
            int gx = x0 - 1 + p % HALO_W;
            uint4 vh = make_uint4(0, 0, 0, 0), vl = vh;
            if ((unsigned)gy < (unsigned)Himg && (unsigned)gx < (unsigned)Wimg) {
                size_t pix = (size_t)b * 65536 + gy * 256 + gx;
                vh = gh4[pix * 4 + chunk];
                vl = gh4[pix * 4 + chunk + (HLO32 >> 2)];
            }
            *(uint4*)(sm + A_OFF + a_byte(p, chunk))     = vh;
            *(uint4*)(sm + A_OFF + a_byte(p, 4 + chunk)) = vl;
        }
    }
    __syncthreads();

    // ---- compute: warp = 2 output rows; per row 2 m-blocks, 4 n-blocks ----
    const int wid  = tid >> 5;            // 0..7
    const int lane = tid & 31;
    const int r0   = wid * 2;             // rows r0, r0+1
    const int lm   = lane & 15;
    const int ksel = (lane >> 4) & 1;     // A: k-chunk select; B: n-pair half

    float acc[2][2][4][4];                // [row][mb][nb][4]
    #pragma unroll
    for (int rr = 0; rr < 2; rr++)
        #pragma unroll
        for (int mb = 0; mb < 2; mb++)
            #pragma unroll
            for (int nb = 0; nb < 4; nb++)
                #pragma unroll
                for (int e = 0; e < 4; e++)
                    acc[rr][mb][nb][e] = 0.0f;

    #pragma unroll
    for (int dy = 0; dy < 3; dy++) {
        #pragma unroll
        for (int dx = 0; dx < 3; dx++) {
            const int tap = dy * 3 + dx;
            #pragma unroll
            for (int kb = 0; kb < 2; kb++) {
                // B frags: 2 n-pairs x (hi,lo), each ldmx4t covers n=16
                uint32_t Bh[2][4], Bl[2][4];
                const int krow = kb * 16 + lm;
                #pragma unroll
                for (int np = 0; np < 2; np++) {
                    uint32_t wb = tap * 2048 + w_byte(krow, np * 2 + ksel);
                    ldmx4t(Bh[np], smb + WH_OFF + wb);
                    ldmx4t(Bl[np], smb + WL_OFF + wb);
                }
                // A frags: 2 rows x 2 mb x (hi,lo)
                uint32_t Ah[2][2][4], Al[2][2][4];
                #pragma unroll
                for (int rr = 0; rr < 2; rr++) {
                    const int pbase = (r0 + rr + dy) * HALO_W + dx;
                    #pragma unroll
                    for (int mb = 0; mb < 2; mb++) {
                        const int p = pbase + mb * 16 + lm;
                        ldmx4(Ah[rr][mb], smb + A_OFF + a_byte(p, kb * 2 + ksel));
                        ldmx4(Al[rr][mb], smb + A_OFF + a_byte(p, 4 + kb * 2 + ksel));
                    }
                }
                #pragma unroll
                for (int rr = 0; rr < 2; rr++)
                    #pragma unroll
                    for (int mb = 0; mb < 2; mb++)
                        #pragma unroll
                        for (int np = 0; np < 2; np++) {
                            mma16816(acc[rr][mb][np * 2],     Ah[rr][mb], &Bh[np][0]);
                            mma16816(acc[rr][mb][np * 2 + 1], Ah[rr][mb], &Bh[np][2]);
                            mma16816(acc[rr][mb][np * 2],     Al[rr][mb], &Bh[np][0]);
                            mma16816(acc[rr][mb][np * 2 + 1], Al[rr][mb], &Bh[np][2]);
                            mma16816(acc[rr][mb][np * 2],     Ah[rr][mb], &Bl[np][0]);
                            mma16816(acc[rr][mb][np * 2 + 1], Ah[rr][mb], &Bl[np][2]);
                        }
            }
        }
    }

    // ---- epilogue ----
    const float* bs = (const float*)(sm + BIAS_OFF);
    const float* gs = (const float*)(sm + GATE_OFF);
    const int grp = lane >> 2, tig = lane & 3;

    #pragma unroll
    for (int rr = 0; rr < 2; rr++) {
        const int y = y0 + r0 + rr;
        #pragma unroll
        for (int mb = 0; mb < 2; mb++) {
            #pragma unroll
            for (int half = 0; half < 2; half++) {
                const int xg = x0 + mb * 16 + grp + half * 8;
                #pragma unroll
                for (int nb = 0; nb < 4; nb++) {
                    const int co = nb * 8 + tig * 2;
                    float v0 = acc[rr][mb][nb][half * 2 + 0];
                    float v1 = acc[rr][mb][nb][half * 2 + 1];
                    float t0 = fmaxf((v0 + bs[co])     * gs[co],     0.0f);
                    float t1 = fmaxf((v1 + bs[co + 1]) * gs[co + 1], 0.0f);
                    if (SECOND) {
                        size_t i0 = (((size_t)b * Cch + co)     * Himg + y) * Wimg + xg;
                        size_t i1 = (((size_t)b * Cch + co + 1) * Himg + y) * Wimg + xg;
                        out[i0] = t0 + x[i0];
                        out[i1] = t1 + x[i1];
                    } else {
                        __nv_bfloat16 h0 = __float2bfloat16(t0);
                        __nv_bfloat16 h1 = __float2bfloat16(t1);
                        __nv_bfloat16 l0 = __float2bfloat16(t0 - __bfloat162float(h0));
                        __nv_bfloat16 l1 = __float2bfloat16(t1 - __bfloat162float(h1));
                        uint32_t uh = (uint32_t)__bfloat16_as_ushort(h0)
                                    | ((uint32_t)__bfloat16_as_ushort(h1) << 16);
                        uint32_t ul = (uint32_t)__bfloat16_as_ushort(l0)
                                    | ((uint32_t)__bfloat16_as_ushort(l1) << 16);
                        size_t pix = (size_t)b * 65536 + y * 256 + xg;
                        g_h[pix * 16 + (co >> 1)]         = uh;
                        g_h[pix * 16 + (co >> 1) + HLO32] = ul;
                    }
                }
            }
        }
    }
}

extern "C" void kernel_launch(void* const* d_in, const int* in_sizes, int n_in,
                              void* d_out, int out_size)
{
    const float* x    = (const float*)d_in[0];
    const float* gate = (const float*)d_in[1];
    const float* w1   = (const float*)d_in[2];
    const float* b1   = (const float*)d_in[3];
    const float* w2   = (const float*)d_in[4];
    const float* b2   = (const float*)d_in[5];
    float*       out  = (float*)d_out;
    (void)in_sizes; (void)n_in; (void)out_size;

    cudaFuncSetAttribute(conv_hmma<false>,
                         cudaFuncAttributeMaxDynamicSharedMemorySize, SMEM_BYTES);
    cudaFuncSetAttribute(conv_hmma<true>,
                         cudaFuncAttributeMaxDynamicSharedMemorySize, SMEM_BYTES);

    dim3 grid(Wimg / TILE_W, Himg / TILE_H, Bsz);   // 8 x 16 x 16 = 2048 CTAs

    conv_hmma<false><<<grid, THREADS, SMEM_BYTES>>>(x, w1, b1, gate, nullptr);
    conv_hmma<true ><<<grid, THREADS, SMEM_BYTES>>>(x, w2, b2, gate, out);
}

// round 7
// speedup vs baseline: 2.0730x; 2.0730x over previous
#include <cuda_runtime.h>
#include <cuda_fp16.h>
#include <cstdint>

#define Bsz  16
#define Cch  32
#define Himg 256
#define Wimg 256

#define TILE_H 16
#define TILE_W 32
#define HALO_W 34
#define NPIX   612            // 18 rows x 34 cols

#define THREADS 256

// smem byte offsets
#define A_OFF    0
#define WH_OFF   (NPIX * 64)             // 39168
#define WL_OFF   (WH_OFF + 9 * 2048)     // 57600
#define BIAS_OFF (WL_OFF + 9 * 2048)     // 76032
#define GATE_OFF (BIAS_OFF + 128)
#define SMEM_BYTES (GATE_OFF + 128)      // 76288  -> 2 CTAs/SM

// h scratch: per pixel 32 fp16 = 16 uint32, single plane. 64 MB.
#define HPIX   (16u * 65536u)            // Bsz*Himg*Wimg
__device__ uint32_t g_h[(size_t)HPIX * 16u];

// ---------------- helpers ----------------
__device__ __forceinline__ uint32_t smem_u32(const void* p) {
    uint32_t a;
    asm("{ .reg .u64 t; cvta.to.shared.u64 t, %1; cvt.u32.u64 %0, t; }"
        : "=r"(a) : "l"(p));
    return a;
}
__device__ __forceinline__ void ldmx4(uint32_t* d, uint32_t a) {
    asm volatile("ldmatrix.sync.aligned.m8n8.x4.shared.b16 {%0,%1,%2,%3}, [%4];"
                 : "=r"(d[0]), "=r"(d[1]), "=r"(d[2]), "=r"(d[3]) : "r"(a));
}
__device__ __forceinline__ void ldmx4t(uint32_t* d, uint32_t a) {
    asm volatile("ldmatrix.sync.aligned.m8n8.x4.trans.shared.b16 {%0,%1,%2,%3}, [%4];"
                 : "=r"(d[0]), "=r"(d[1]), "=r"(d[2]), "=r"(d[3]) : "r"(a));
}
__device__ __forceinline__ void mma16816(float* c, const uint32_t* a, const uint32_t* b) {
    asm volatile("mma.sync.aligned.m16n8k16.row.col.f32.f16.f16.f32 "
                 "{%0,%1,%2,%3}, {%4,%5,%6,%7}, {%8,%9}, {%0,%1,%2,%3};"
                 : "+f"(c[0]), "+f"(c[1]), "+f"(c[2]), "+f"(c[3])
                 : "r"(a[0]), "r"(a[1]), "r"(a[2]), "r"(a[3]),
                   "r"(b[0]), "r"(b[1]));
}

// A-tile: pixel p -> 64B (4 granules of 16B = 8 ci fp16).
// Swizzle keeps 8-row ldmatrix wavefronts conflict-free (incl. p vs p+4).
__device__ __forceinline__ uint32_t a_byte(int p, int kc) {
    return (uint32_t)(p * 64 + (((kc + p + (p >> 2)) & 3) << 4));
}
// W-tile within one tap: row ci (64B = 32 co fp16), granule nb = co/8
__device__ __forceinline__ uint32_t w_byte(int ci, int nb) {
    return (uint32_t)(ci * 64 + (((nb + ((ci >> 1) & 3)) & 3) << 4));
}

// ---------------- kernel ----------------
template <bool SECOND>
__global__ __launch_bounds__(THREADS, 2)
void conv_hmma(const float* __restrict__ x,
               const float* __restrict__ w,
               const float* __restrict__ bias,
               const float* __restrict__ gate,
               float* __restrict__ out)
{
    extern __shared__ char sm[];
    const uint32_t smb = smem_u32(sm);
    const int tid = threadIdx.x;
    const int b  = blockIdx.z;
    const int y0 = blockIdx.y * TILE_H;
    const int x0 = blockIdx.x * TILE_W;

    // ---- weights -> [tap][ci][co] fp16 hi/lo, swizzled ----
    for (int i = tid; i < Cch * Cch * 9; i += THREADS) {
        int co = i / 288, rem = i - co * 288;
        int ci = rem / 9, tap = rem - ci * 9;
        float v = w[i];
        __half hh = __float2half(v);
        __half ll = __float2half(v - __half2float(hh));
        uint32_t byte = tap * 2048 + w_byte(ci, co >> 3) + ((co & 7) << 1);
        *(__half*)(sm + WH_OFF + byte) = hh;
        *(__half*)(sm + WL_OFF + byte) = ll;
    }
    if (tid < 32) {
        ((float*)(sm + BIAS_OFF))[tid] = bias[tid];
        float g = gate[b * 32 + tid];
        ((float*)(sm + GATE_OFF))[tid] = (g > 0.0f) ? g : 0.0f;
    }

    // ---- A tile fill (channels-last fp16, single plane, swizzled) ----
    if (!SECOND) {
        for (int i = tid; i < NPIX * 32; i += THREADS) {
            int ci = i / NPIX, p = i - ci * NPIX;
            int gy = y0 - 1 + p / HALO_W;
            int gx = x0 - 1 + p % HALO_W;
            float v = 0.0f;
            if ((unsigned)gy < (unsigned)Himg && (unsigned)gx < (unsigned)Wimg)
                v = x[(((size_t)b * Cch + ci) * Himg + gy) * Wimg + gx];
            *(__half*)(sm + A_OFF + a_byte(p, ci >> 3) + ((ci & 7) << 1)) =
                __float2half(v);
        }
    } else {
        const uint4* gh4 = (const uint4*)g_h;
        for (int i = tid; i < NPIX * 4; i += THREADS) {
            int p = i >> 2, chunk = i & 3;
            int gy = y0 - 1 + p / HALO_W;
            int gx = x0 - 1 + p % HALO_W;
            uint4 vh = make_uint4(0, 0, 0, 0);
            if ((unsigned)gy < (unsigned)Himg && (unsigned)gx < (unsigned)Wimg) {
                size_t pix = (size_t)b * 65536 + gy * 256 + gx;
                vh = gh4[pix * 4 + chunk];
            }
            *(uint4*)(sm + A_OFF + a_byte(p, chunk)) = vh;
        }
    }
    __syncthreads();

    // ---- compute: warp = 2 rows; per row 2 m-blocks; 4 n-blocks via 2 np ----
    const int wid  = tid >> 5;            // 0..7
    const int lane = tid & 31;
    const int r0   = wid * 2;
    const int lm   = lane & 15;
    const int ksel = (lane >> 4) & 1;     // A: k-granule select; B: n-block half

    float acc[2][2][4][4];                // [row][mb][nb][4]
    #pragma unroll
    for (int rr = 0; rr < 2; rr++)
        #pragma unroll
        for (int mb = 0; mb < 2; mb++)
            #pragma unroll
            for (int nb = 0; nb < 4; nb++)
                #pragma unroll
                for (int e = 0; e < 4; e++)
                    acc[rr][mb][nb][e] = 0.0f;

    #pragma unroll
    for (int dy = 0; dy < 3; dy++) {
        #pragma unroll
        for (int dx = 0; dx < 3; dx++) {
            const int tap = dy * 3 + dx;
            #pragma unroll
            for (int kb = 0; kb < 2; kb++) {
                // A frags (hi only): 2 rows x 2 mb
                uint32_t Ah[2][2][4];
                #pragma unroll
                for (int rr = 0; rr < 2; rr++) {
                    const int pbase = (r0 + rr + dy) * HALO_W + dx;
                    #pragma unroll
                    for (int mb = 0; mb < 2; mb++) {
                        const int p = pbase + mb * 16 + lm;
                        ldmx4(Ah[rr][mb], smb + A_OFF + a_byte(p, kb * 2 + ksel));
                    }
                }
                const int krow = kb * 16 + lm;
                #pragma unroll
                for (int np = 0; np < 2; np++) {
                    uint32_t Bh[4], Bl[4];
                    uint32_t wb = tap * 2048 + w_byte(krow, np * 2 + ksel);
                    ldmx4t(Bh, smb + WH_OFF + wb);
                    ldmx4t(Bl, smb + WL_OFF + wb);
                    #pragma unroll
                    for (int rr = 0; rr < 2; rr++)
                        #pragma unroll
                        for (int mb = 0; mb < 2; mb++) {
                            mma16816(acc[rr][mb][np * 2],     Ah[rr][mb], &Bh[0]);
                            mma16816(acc[rr][mb][np * 2 + 1], Ah[rr][mb], &Bh[2]);
                            mma16816(acc[rr][mb][np * 2],     Ah[rr][mb], &Bl[0]);
                            mma16816(acc[rr][mb][np * 2 + 1], Ah[rr][mb], &Bl[2]);
                        }
                }
            }
        }
    }

    // ---- epilogue ----
    const float* bs = (const float*)(sm + BIAS_OFF);
    const float* gs = (const float*)(sm + GATE_OFF);
    const int grp = lane >> 2, tig = lane & 3;

    #pragma unroll
    for (int rr = 0; rr < 2; rr++) {
        const int y = y0 + r0 + rr;
        #pragma unroll
        for (int mb = 0; mb < 2; mb++) {
            #pragma unroll
            for (int half = 0; half < 2; half++) {
                const int xg = x0 + mb * 16 + grp + half * 8;
                #pragma unroll
                for (int nb = 0; nb < 4; nb++) {
                    const int co = nb * 8 + tig * 2;
                    float v0 = acc[rr][mb][nb][half * 2 + 0];
                    float v1 = acc[rr][mb][nb][half * 2 + 1];
                    float t0 = fmaxf((v0 + bs[co])     * gs[co],     0.0f);
                    float t1 = fmaxf((v1 + bs[co + 1]) * gs[co + 1], 0.0f);
                    if (SECOND) {
                        size_t i0 = (((size_t)b * Cch + co)     * Himg + y) * Wimg + xg;
                        size_t i1 = (((size_t)b * Cch + co + 1) * Himg + y) * Wimg + xg;
                        out[i0] = t0 + x[i0];
                        out[i1] = t1 + x[i1];
                    } else {
                        __half h0 = __float2half(t0);
                        __half h1 = __float2half(t1);
                        uint32_t uh = (uint32_t)__half_as_ushort(h0)
                                    | ((uint32_t)__half_as_ushort(h1) << 16);
                        size_t pix = (size_t)b * 65536 + y * 256 + xg;
                        g_h[pix * 16 + (co >> 1)] = uh;
                    }
                }
            }
        }
    }
}

extern "C" void kernel_launch(void* const* d_in, const int* in_sizes, int n_in,
                              void* d_out, int out_size)
{
    const float* x    = (const float*)d_in[0];
    const float* gate = (const float*)d_in[1];
    const float* w1   = (const float*)d_in[2];
    const float* b1   = (const float*)d_in[3];
    const float* w2   = (const float*)d_in[4];
    const float* b2   = (const float*)d_in[5];
    float*       out  = (float*)d_out;
    (void)in_sizes; (void)n_in; (void)out_size;

    cudaFuncSetAttribute(conv_hmma<false>,
                         cudaFuncAttributeMaxDynamicSharedMemorySize, SMEM_BYTES);
    cudaFuncSetAttribute(conv_hmma<true>,
                         cudaFuncAttributeMaxDynamicSharedMemorySize, SMEM_BYTES);

    dim3 grid(Wimg / TILE_W, Himg / TILE_H, Bsz);   // 8 x 16 x 16 = 2048 CTAs

    conv_hmma<false><<<grid, THREADS, SMEM_BYTES>>>(x, w1, b1, gate, nullptr);
    conv_hmma<true ><<<grid, THREADS, SMEM_BYTES>>>(x, w2, b2, gate, out);
}

// round 8
// speedup vs baseline: 2.5395x; 1.2250x over previous
#include <cuda_runtime.h>
#include <cuda_fp16.h>
#include <cstdint>

#define Bsz  16
#define Cch  32
#define Himg 256
#define Wimg 256

#define TILE_H 16
#define TILE_W 32
#define HALO_W 34
#define NPIX   612            // 18 rows x 34 cols

#define THREADS 256

// smem byte offsets
#define A_OFF    0
#define WH_OFF   (NPIX * 64)             // 39168
#define BIAS_OFF (WH_OFF + 9 * 2048)     // 57600
#define GATE_OFF (BIAS_OFF + 128)
#define SMEM_BYTES (GATE_OFF + 128)      // 57856  -> 2 CTAs/SM

// h scratch: per pixel 32 fp16 = 16 uint32, single plane. 64 MB.
#define HPIX   (16u * 65536u)            // Bsz*Himg*Wimg
__device__ uint32_t g_h[(size_t)HPIX * 16u];

// ---------------- helpers ----------------
__device__ __forceinline__ uint32_t smem_u32(const void* p) {
    uint32_t a;
    asm("{ .reg .u64 t; cvta.to.shared.u64 t, %1; cvt.u32.u64 %0, t; }"
        : "=r"(a) : "l"(p));
    return a;
}
__device__ __forceinline__ void ldmx4(uint32_t* d, uint32_t a) {
    asm volatile("ldmatrix.sync.aligned.m8n8.x4.shared.b16 {%0,%1,%2,%3}, [%4];"
                 : "=r"(d[0]), "=r"(d[1]), "=r"(d[2]), "=r"(d[3]) : "r"(a));
}
__device__ __forceinline__ void ldmx4t(uint32_t* d, uint32_t a) {
    asm volatile("ldmatrix.sync.aligned.m8n8.x4.trans.shared.b16 {%0,%1,%2,%3}, [%4];"
                 : "=r"(d[0]), "=r"(d[1]), "=r"(d[2]), "=r"(d[3]) : "r"(a));
}
__device__ __forceinline__ void mma16816(float* c, const uint32_t* a, const uint32_t* b) {
    asm volatile("mma.sync.aligned.m16n8k16.row.col.f32.f16.f16.f32 "
                 "{%0,%1,%2,%3}, {%4,%5,%6,%7}, {%8,%9}, {%0,%1,%2,%3};"
                 : "+f"(c[0]), "+f"(c[1]), "+f"(c[2]), "+f"(c[3])
                 : "r"(a[0]), "r"(a[1]), "r"(a[2]), "r"(a[3]),
                   "r"(b[0]), "r"(b[1]));
}

// A-tile: pixel p -> 64B (4 granules of 16B = 8 ci fp16).
__device__ __forceinline__ uint32_t a_byte(int p, int kc) {
    return (uint32_t)(p * 64 + (((kc + p + (p >> 2)) & 3) << 4));
}
// W-tile within one tap: row ci (64B = 32 co fp16), granule nb = co/8
__device__ __forceinline__ uint32_t w_byte(int ci, int nb) {
    return (uint32_t)(ci * 64 + (((nb + ((ci >> 1) & 3)) & 3) << 4));
}

// ---------------- kernel ----------------
template <bool SECOND>
__global__ __launch_bounds__(THREADS, 2)
void conv_hmma(const float* __restrict__ x,
               const float* __restrict__ w,
               const float* __restrict__ bias,
               const float* __restrict__ gate,
               float* __restrict__ out)
{
    extern __shared__ char sm[];
    const uint32_t smb = smem_u32(sm);
    const int tid = threadIdx.x;
    const int b  = blockIdx.z;
    const int y0 = blockIdx.y * TILE_H;
    const int x0 = blockIdx.x * TILE_W;

    // ---- weights -> [tap][ci][co] fp16, swizzled ----
    for (int i = tid; i < Cch * Cch * 9; i += THREADS) {
        int co = i / 288, rem = i - co * 288;
        int ci = rem / 9, tap = rem - ci * 9;
        uint32_t byte = tap * 2048 + w_byte(ci, co >> 3) + ((co & 7) << 1);
        *(__half*)(sm + WH_OFF + byte) = __float2half(w[i]);
    }
    if (tid < 32) {
        ((float*)(sm + BIAS_OFF))[tid] = bias[tid];
        float g = gate[b * 32 + tid];
        ((float*)(sm + GATE_OFF))[tid] = (g > 0.0f) ? g : 0.0f;
    }

    // ---- A tile fill (channels-last fp16, swizzled) ----
    if (!SECOND) {
        for (int i = tid; i < NPIX * 32; i += THREADS) {
            int ci = i / NPIX, p = i - ci * NPIX;
            int gy = y0 - 1 + p / HALO_W;
            int gx = x0 - 1 + p % HALO_W;
            float v = 0.0f;
            if ((unsigned)gy < (unsigned)Himg && (unsigned)gx < (unsigned)Wimg)
                v = x[(((size_t)b * Cch + ci) * Himg + gy) * Wimg + gx];
            *(__half*)(sm + A_OFF + a_byte(p, ci >> 3) + ((ci & 7) << 1)) =
                __float2half(v);
        }
    } else {
        const uint4* gh4 = (const uint4*)g_h;
        for (int i = tid; i < NPIX * 4; i += THREADS) {
            int p = i >> 2, chunk = i & 3;
            int gy = y0 - 1 + p / HALO_W;
            int gx = x0 - 1 + p % HALO_W;
            uint4 vh = make_uint4(0, 0, 0, 0);
            if ((unsigned)gy < (unsigned)Himg && (unsigned)gx < (unsigned)Wimg) {
                size_t pix = (size_t)b * 65536 + gy * 256 + gx;
                vh = gh4[pix * 4 + chunk];
            }
            *(uint4*)(sm + A_OFF + a_byte(p, chunk)) = vh;
        }
    }
    __syncthreads();

    // ---- compute: warp = 2 rows; per row 2 m-blocks; 4 n-blocks via 2 np ----
    const int wid  = tid >> 5;            // 0..7
    const int lane = tid & 31;
    const int r0   = wid * 2;
    const int lm   = lane & 15;
    const int ksel = (lane >> 4) & 1;     // A: k-granule select; B: n-block half

    float acc[2][2][4][4];                // [row][mb][nb][4]
    #pragma unroll
    for (int rr = 0; rr < 2; rr++)
        #pragma unroll
        for (int mb = 0; mb < 2; mb++)
            #pragma unroll
            for (int nb = 0; nb < 4; nb++)
                #pragma unroll
                for (int e = 0; e < 4; e++)
                    acc[rr][mb][nb][e] = 0.0f;

    #pragma unroll
    for (int dy = 0; dy < 3; dy++) {
        #pragma unroll
        for (int dx = 0; dx < 3; dx++) {
            const int tap = dy * 3 + dx;
            #pragma unroll
            for (int kb = 0; kb < 2; kb++) {
                // A frags: 2 rows x 2 mb
                uint32_t Ah[2][2][4];
                #pragma unroll
                for (int rr = 0; rr < 2; rr++) {
                    const int pbase = (r0 + rr + dy) * HALO_W + dx;
                    #pragma unroll
                    for (int mb = 0; mb < 2; mb++) {
                        const int p = pbase + mb * 16 + lm;
                        ldmx4(Ah[rr][mb], smb + A_OFF + a_byte(p, kb * 2 + ksel));
                    }
                }
                const int krow = kb * 16 + lm;
                #pragma unroll
                for (int np = 0; np < 2; np++) {
                    uint32_t Bh[4];
                    ldmx4t(Bh, smb + WH_OFF + tap * 2048 + w_byte(krow, np * 2 + ksel));
                    #pragma unroll
                    for (int rr = 0; rr < 2; rr++)
                        #pragma unroll
                        for (int mb = 0; mb < 2; mb++) {
                            mma16816(acc[rr][mb][np * 2],     Ah[rr][mb], &Bh[0]);
                            mma16816(acc[rr][mb][np * 2 + 1], Ah[rr][mb], &Bh[2]);
                        }
                }
            }
        }
    }

    // ---- epilogue ----
    const float* bs = (const float*)(sm + BIAS_OFF);
    const float* gs = (const float*)(sm + GATE_OFF);
    const int grp = lane >> 2, tig = lane & 3;

    #pragma unroll
    for (int rr = 0; rr < 2; rr++) {
        const int y = y0 + r0 + rr;
        #pragma unroll
        for (int mb = 0; mb < 2; mb++) {
            #pragma unroll
            for (int half = 0; half < 2; half++) {
                const int xg = x0 + mb * 16 + grp + half * 8;
                #pragma unroll
                for (int nb = 0; nb < 4; nb++) {
                    const int co = nb * 8 + tig * 2;
                    float v0 = acc[rr][mb][nb][half * 2 + 0];
                    float v1 = acc[rr][mb][nb][half * 2 + 1];
                    float t0 = fmaxf((v0 + bs[co])     * gs[co],     0.0f);
                    float t1 = fmaxf((v1 + bs[co + 1]) * gs[co + 1], 0.0f);
                    if (SECOND) {
                        size_t i0 = (((size_t)b * Cch + co)     * Himg + y) * Wimg + xg;
                        size_t i1 = (((size_t)b * Cch + co + 1) * Himg + y) * Wimg + xg;
                        out[i0] = t0 + x[i0];
                        out[i1] = t1 + x[i1];
                    } else {
                        __half h0 = __float2half(t0);
                        __half h1 = __float2half(t1);
                        uint32_t uh = (uint32_t)__half_as_ushort(h0)
                                    | ((uint32_t)__half_as_ushort(h1) << 16);
                        size_t pix = (size_t)b * 65536 + y * 256 + xg;
                        g_h[pix * 16 + (co >> 1)] = uh;
                    }
                }
            }
        }
    }
}

extern "C" void kernel_launch(void* const* d_in, const int* in_sizes, int n_in,
                              void* d_out, int out_size)
{
    const float* x    = (const float*)d_in[0];
    const float* gate = (const float*)d_in[1];
    const float* w1   = (const float*)d_in[2];
    const float* b1   = (const float*)d_in[3];
    const float* w2   = (const float*)d_in[4];
    const float* b2   = (const float*)d_in[5];
    float*       out  = (float*)d_out;
    (void)in_sizes; (void)n_in; (void)out_size;

    cudaFuncSetAttribute(conv_hmma<false>,
                         cudaFuncAttributeMaxDynamicSharedMemorySize, SMEM_BYTES);
    cudaFuncSetAttribute(conv_hmma<true>,
                         cudaFuncAttributeMaxDynamicSharedMemorySize, SMEM_BYTES);

    dim3 grid(Wimg / TILE_W, Himg / TILE_H, Bsz);   // 8 x 16 x 16 = 2048 CTAs

    conv_hmma<false><<<grid, THREADS, SMEM_BYTES>>>(x, w1, b1, gate, nullptr);
    conv_hmma<true ><<<grid, THREADS, SMEM_BYTES>>>(x, w2, b2, gate, out);
}

// round 9
// speedup vs baseline: 2.6815x; 1.0559x over previous
#include <cuda_runtime.h>
#include <cuda_fp16.h>
#include <cstdint>

#define Bsz  16
#define Cch  32
#define Himg 256
#define Wimg 256

#define TILE_H 16
#define TILE_W 32
#define HALO_W 34
#define NPIX   612            // 18 rows x 34 cols

#define THREADS 256

// smem byte offsets
#define A_OFF    0
#define WH_OFF   (NPIX * 64)             // 39168
#define BIAS_OFF (WH_OFF + 9 * 2048)     // 57600
#define GATE_OFF (BIAS_OFF + 128)
#define SMEM_BYTES (GATE_OFF + 128)      // 57856  -> 2 CTAs/SM

// h scratch: per pixel 32 fp16 = 16 uint32, single plane. 64 MB.
#define HPIX   (16u * 65536u)            // Bsz*Himg*Wimg
__device__ uint32_t g_h[(size_t)HPIX * 16u];

// ---------------- helpers ----------------
__device__ __forceinline__ uint32_t smem_u32(const void* p) {
    uint32_t a;
    asm("{ .reg .u64 t; cvta.to.shared.u64 t, %1; cvt.u32.u64 %0, t; }"
        : "=r"(a) : "l"(p));
    return a;
}
__device__ __forceinline__ void ldmx4(uint32_t* d, uint32_t a) {
    asm volatile("ldmatrix.sync.aligned.m8n8.x4.shared.b16 {%0,%1,%2,%3}, [%4];"
                 : "=r"(d[0]), "=r"(d[1]), "=r"(d[2]), "=r"(d[3]) : "r"(a));
}
__device__ __forceinline__ void ldmx4t(uint32_t* d, uint32_t a) {
    asm volatile("ldmatrix.sync.aligned.m8n8.x4.trans.shared.b16 {%0,%1,%2,%3}, [%4];"
                 : "=r"(d[0]), "=r"(d[1]), "=r"(d[2]), "=r"(d[3]) : "r"(a));
}
__device__ __forceinline__ void mma16816(float* c, const uint32_t* a, const uint32_t* b) {
    asm volatile("mma.sync.aligned.m16n8k16.row.col.f32.f16.f16.f32 "
                 "{%0,%1,%2,%3}, {%4,%5,%6,%7}, {%8,%9}, {%0,%1,%2,%3};"
                 : "+f"(c[0]), "+f"(c[1]), "+f"(c[2]), "+f"(c[3])
                 : "r"(a[0]), "r"(a[1]), "r"(a[2]), "r"(a[3]),
                   "r"(b[0]), "r"(b[1]));
}

// A-tile: pixel p -> 64B (4 granules of 16B = 8 ci fp16).
__device__ __forceinline__ uint32_t a_byte(int p, int kc) {
    return (uint32_t)(p * 64 + (((kc + p + (p >> 2)) & 3) << 4));
}
// W-tile within one tap: row ci (64B = 32 co fp16), granule nb = co/8
__device__ __forceinline__ uint32_t w_byte(int ci, int nb) {
    return (uint32_t)(ci * 64 + (((nb + ((ci >> 1) & 3)) & 3) << 4));
}

// ---------------- kernel ----------------
template <bool SECOND>
__global__ __launch_bounds__(THREADS, 2)
void conv_hmma(const float* __restrict__ x,
               const float* __restrict__ w,
               const float* __restrict__ bias,
               const float* __restrict__ gate,
               float* __restrict__ out)
{
    extern __shared__ char sm[];
    const uint32_t smb = smem_u32(sm);
    const int tid = threadIdx.x;
    const int b  = blockIdx.z;
    const int y0 = blockIdx.y * TILE_H;
    const int x0 = blockIdx.x * TILE_W;

    // ---- weights -> [tap][ci][co] fp16, swizzled ----
    for (int i = tid; i < Cch * Cch * 9; i += THREADS) {
        int co = i / 288, rem = i - co * 288;
        int ci = rem / 9, tap = rem - ci * 9;
        uint32_t byte = tap * 2048 + w_byte(ci, co >> 3) + ((co & 7) << 1);
        *(__half*)(sm + WH_OFF + byte) = __float2half(w[i]);
    }
    if (tid < 32) {
        ((float*)(sm + BIAS_OFF))[tid] = bias[tid];
        float g = gate[b * 32 + tid];
        ((float*)(sm + GATE_OFF))[tid] = (g > 0.0f) ? g : 0.0f;
    }

    // ---- A tile fill (channels-last fp16, swizzled) ----
    if (!SECOND) {
        for (int i = tid; i < NPIX * 32; i += THREADS) {
            int ci = i / NPIX, p = i - ci * NPIX;
            int gy = y0 - 1 + p / HALO_W;
            int gx = x0 - 1 + p % HALO_W;
            float v = 0.0f;
            if ((unsigned)gy < (unsigned)Himg && (unsigned)gx < (unsigned)Wimg)
                v = x[(((size_t)b * Cch + ci) * Himg + gy) * Wimg + gx];
            *(__half*)(sm + A_OFF + a_byte(p, ci >> 3) + ((ci & 7) << 1)) =
                __float2half(v);
        }
    } else {
        const uint4* gh4 = (const uint4*)g_h;
        for (int i = tid; i < NPIX * 4; i += THREADS) {
            int p = i >> 2, chunk = i & 3;
            int gy = y0 - 1 + p / HALO_W;
            int gx = x0 - 1 + p % HALO_W;
            uint4 vh = make_uint4(0, 0, 0, 0);
            if ((unsigned)gy < (unsigned)Himg && (unsigned)gx < (unsigned)Wimg) {
                size_t pix = (size_t)b * 65536 + gy * 256 + gx;
                vh = gh4[pix * 4 + chunk];
            }
            *(uint4*)(sm + A_OFF + a_byte(p, chunk)) = vh;
        }
    }
    __syncthreads();

    // ---- compute: warp = 2 rows; A rows shared across dy ----
    const int wid  = tid >> 5;            // 0..7
    const int lane = tid & 31;
    const int r0   = wid * 2;
    const int lm   = lane & 15;
    const int ksel = (lane >> 4) & 1;     // A: k-granule select; B: n-block half

    float acc[2][2][4][4];                // [row][mb][nb][4]
    #pragma unroll
    for (int rr = 0; rr < 2; rr++)
        #pragma unroll
        for (int mb = 0; mb < 2; mb++)
            #pragma unroll
            for (int nb = 0; nb < 4; nb++)
                #pragma unroll
                for (int e = 0; e < 4; e++)
                    acc[rr][mb][nb][e] = 0.0f;

    #pragma unroll
    for (int kb = 0; kb < 2; kb++) {
        const int krow = kb * 16 + lm;
        #pragma unroll
        for (int dx = 0; dx < 3; dx++) {
            // A frags for the 4 distinct input rows (r0..r0+3), 2 m-blocks
            uint32_t Ah[4][2][4];
            #pragma unroll
            for (int rw = 0; rw < 4; rw++) {
                const int pbase = (r0 + rw) * HALO_W + dx;
                #pragma unroll
                for (int mb = 0; mb < 2; mb++) {
                    const int p = pbase + mb * 16 + lm;
                    ldmx4(Ah[rw][mb], smb + A_OFF + a_byte(p, kb * 2 + ksel));
                }
            }
            #pragma unroll
            for (int dy = 0; dy < 3; dy++) {
                const int tap = dy * 3 + dx;
                #pragma unroll
                for (int np = 0; np < 2; np++) {
                    uint32_t Bh[4];
                    ldmx4t(Bh, smb + WH_OFF + tap * 2048 + w_byte(krow, np * 2 + ksel));
                    #pragma unroll
                    for (int rr = 0; rr < 2; rr++)
                        #pragma unroll
                        for (int mb = 0; mb < 2; mb++) {
                            mma16816(acc[rr][mb][np * 2],     Ah[rr + dy][mb], &Bh[0]);
                            mma16816(acc[rr][mb][np * 2 + 1], Ah[rr + dy][mb], &Bh[2]);
                        }
                }
            }
        }
    }

    // ---- epilogue ----
    const float* bs = (const float*)(sm + BIAS_OFF);
    const float* gs = (const float*)(sm + GATE_OFF);
    const int grp = lane >> 2, tig = lane & 3;

    #pragma unroll
    for (int rr = 0; rr < 2; rr++) {
        const int y = y0 + r0 + rr;
        #pragma unroll
        for (int mb = 0; mb < 2; mb++) {
            #pragma unroll
            for (int half = 0; half < 2; half++) {
                const int xg = x0 + mb * 16 + grp + half * 8;
                #pragma unroll
                for (int nb = 0; nb < 4; nb++) {
                    const int co = nb * 8 + tig * 2;
                    float v0 = acc[rr][mb][nb][half * 2 + 0];
                    float v1 = acc[rr][mb][nb][half * 2 + 1];
                    float t0 = fmaxf((v0 + bs[co])     * gs[co],     0.0f);
                    float t1 = fmaxf((v1 + bs[co + 1]) * gs[co + 1], 0.0f);
                    if (SECOND) {
                        size_t i0 = (((size_t)b * Cch + co)     * Himg + y) * Wimg + xg;
                        size_t i1 = (((size_t)b * Cch + co + 1) * Himg + y) * Wimg + xg;
                        out[i0] = t0 + x[i0];
                        out[i1] = t1 + x[i1];
                    } else {
                        __half h0 = __float2half(t0);
                        __half h1 = __float2half(t1);
                        uint32_t uh = (uint32_t)__half_as_ushort(h0)
                                    | ((uint32_t)__half_as_ushort(h1) << 16);
                        size_t pix = (size_t)b * 65536 + y * 256 + xg;
                        g_h[pix * 16 + (co >> 1)] = uh;
                    }
                }
            }
        }
    }
}

extern "C" void kernel_launch(void* const* d_in, const int* in_sizes, int n_in,
                              void* d_out, int out_size)
{
    const float* x    = (const float*)d_in[0];
    const float* gate = (const float*)d_in[1];
    const float* w1   = (const float*)d_in[2];
    const float* b1   = (const float*)d_in[3];
    const float* w2   = (const float*)d_in[4];
    const float* b2   = (const float*)d_in[5];
    float*       out  = (float*)d_out;
    (void)in_sizes; (void)n_in; (void)out_size;

    cudaFuncSetAttribute(conv_hmma<false>,
                         cudaFuncAttributeMaxDynamicSharedMemorySize, SMEM_BYTES);
    cudaFuncSetAttribute(conv_hmma<true>,
                         cudaFuncAttributeMaxDynamicSharedMemorySize, SMEM_BYTES);

    dim3 grid(Wimg / TILE_W, Himg / TILE_H, Bsz);   // 8 x 16 x 16 = 2048 CTAs

    conv_hmma<false><<<grid, THREADS, SMEM_BYTES>>>(x, w1, b1, gate, nullptr);
    conv_hmma<true ><<<grid, THREADS, SMEM_BYTES>>>(x, w2, b2, gate, out);
}

// round 10
// speedup vs baseline: 3.1083x; 1.1592x over previous
#include <cuda_runtime.h>
#include <cuda_fp16.h>
#include <cstdint>

#define Bsz  16
#define Cch  32
#define Himg 256
#define Wimg 256

#define TILE_H 16
#define TILE_W 32
#define HALO_W 34
#define NPIX   612            // 18 rows x 34 cols

#define THREADS 256

// smem byte offsets
#define A_OFF    0
#define WH_OFF   (NPIX * 64)             // 39168
#define BIAS_OFF (WH_OFF + 9 * 2048)     // 57600
#define GATE_OFF (BIAS_OFF + 128)
#define SMEM_BYTES (GATE_OFF + 128)      // 57856  -> 3 CTAs/SM (regs permitting)

// h scratch: per pixel 32 fp16 = 16 uint32, single plane. 64 MB.
#define HPIX   (16u * 65536u)            // Bsz*Himg*Wimg
__device__ uint32_t g_h[(size_t)HPIX * 16u];

// ---------------- helpers ----------------
__device__ __forceinline__ uint32_t smem_u32(const void* p) {
    uint32_t a;
    asm("{ .reg .u64 t; cvta.to.shared.u64 t, %1; cvt.u32.u64 %0, t; }"
        : "=r"(a) : "l"(p));
    return a;
}
__device__ __forceinline__ void ldmx4(uint32_t* d, uint32_t a) {
    asm volatile("ldmatrix.sync.aligned.m8n8.x4.shared.b16 {%0,%1,%2,%3}, [%4];"
                 : "=r"(d[0]), "=r"(d[1]), "=r"(d[2]), "=r"(d[3]) : "r"(a));
}
__device__ __forceinline__ void ldmx4t(uint32_t* d, uint32_t a) {
    asm volatile("ldmatrix.sync.aligned.m8n8.x4.trans.shared.b16 {%0,%1,%2,%3}, [%4];"
                 : "=r"(d[0]), "=r"(d[1]), "=r"(d[2]), "=r"(d[3]) : "r"(a));
}
// fp16-accumulate HMMA: C/D are 2 packed half2 regs
__device__ __forceinline__ void mma16816h(uint32_t* c, const uint32_t* a, const uint32_t* b) {
    asm volatile("mma.sync.aligned.m16n8k16.row.col.f16.f16.f16.f16 "
                 "{%0,%1}, {%2,%3,%4,%5}, {%6,%7}, {%0,%1};"
                 : "+r"(c[0]), "+r"(c[1])
                 : "r"(a[0]), "r"(a[1]), "r"(a[2]), "r"(a[3]),
                   "r"(b[0]), "r"(b[1]));
}

// A-tile: pixel p -> 64B (4 granules of 16B = 8 ci fp16).
__device__ __forceinline__ uint32_t a_byte(int p, int kc) {
    return (uint32_t)(p * 64 + (((kc + p + (p >> 2)) & 3) << 4));
}
// W-tile within one tap: row ci (64B = 32 co fp16), granule nb = co/8
__device__ __forceinline__ uint32_t w_byte(int ci, int nb) {
    return (uint32_t)(ci * 64 + (((nb + ((ci >> 1) & 3)) & 3) << 4));
}

// ---------------- kernel ----------------
template <bool SECOND>
__global__ __launch_bounds__(THREADS, 3)
void conv_hmma(const float* __restrict__ x,
               const float* __restrict__ w,
               const float* __restrict__ bias,
               const float* __restrict__ gate,
               float* __restrict__ out)
{
    extern __shared__ char sm[];
    const uint32_t smb = smem_u32(sm);
    const int tid = threadIdx.x;
    const int b  = blockIdx.z;
    const int y0 = blockIdx.y * TILE_H;
    const int x0 = blockIdx.x * TILE_W;

    // ---- weights -> [tap][ci][co] fp16, swizzled ----
    for (int i = tid; i < Cch * Cch * 9; i += THREADS) {
        int co = i / 288, rem = i - co * 288;
        int ci = rem / 9, tap = rem - ci * 9;
        uint32_t byte = tap * 2048 + w_byte(ci, co >> 3) + ((co & 7) << 1);
        *(__half*)(sm + WH_OFF + byte) = __float2half(w[i]);
    }
    if (tid < 32) {
        ((float*)(sm + BIAS_OFF))[tid] = bias[tid];
        float g = gate[b * 32 + tid];
        ((float*)(sm + GATE_OFF))[tid] = (g > 0.0f) ? g : 0.0f;
    }

    // ---- A tile fill (channels-last fp16, swizzled) ----
    if (!SECOND) {
        for (int i = tid; i < NPIX * 32; i += THREADS) {
            int ci = i / NPIX, p = i - ci * NPIX;
            int gy = y0 - 1 + p / HALO_W;
            int gx = x0 - 1 + p % HALO_W;
            float v = 0.0f;
            if ((unsigned)gy < (unsigned)Himg && (unsigned)gx < (unsigned)Wimg)
                v = x[(((size_t)b * Cch + ci) * Himg + gy) * Wimg + gx];
            *(__half*)(sm + A_OFF + a_byte(p, ci >> 3) + ((ci & 7) << 1)) =
                __float2half(v);
        }
    } else {
        const uint4* gh4 = (const uint4*)g_h;
        for (int i = tid; i < NPIX * 4; i += THREADS) {
            int p = i >> 2, chunk = i & 3;
            int gy = y0 - 1 + p / HALO_W;
            int gx = x0 - 1 + p % HALO_W;
            uint4 vh = make_uint4(0, 0, 0, 0);
            if ((unsigned)gy < (unsigned)Himg && (unsigned)gx < (unsigned)Wimg) {
                size_t pix = (size_t)b * 65536 + gy * 256 + gx;
                vh = gh4[pix * 4 + chunk];
            }
            *(uint4*)(sm + A_OFF + a_byte(p, chunk)) = vh;
        }
    }
    __syncthreads();

    // ---- compute: warp = 2 rows; A rows shared across dy; fp16 acc ----
    const int wid  = tid >> 5;            // 0..7
    const int lane = tid & 31;
    const int r0   = wid * 2;
    const int lm   = lane & 15;
    const int ksel = (lane >> 4) & 1;     // A: k-granule select; B: n-block half

    uint32_t acc[2][2][4][2];             // [row][mb][nb][2 half2]
    #pragma unroll
    for (int rr = 0; rr < 2; rr++)
        #pragma unroll
        for (int mb = 0; mb < 2; mb++)
            #pragma unroll
            for (int nb = 0; nb < 4; nb++) {
                acc[rr][mb][nb][0] = 0u;
                acc[rr][mb][nb][1] = 0u;
            }

    #pragma unroll
    for (int kb = 0; kb < 2; kb++) {
        const int krow = kb * 16 + lm;
        #pragma unroll
        for (int dx = 0; dx < 3; dx++) {
            // A frags for the 4 distinct input rows (r0..r0+3), 2 m-blocks
            uint32_t Ah[4][2][4];
            #pragma unroll
            for (int rw = 0; rw < 4; rw++) {
                const int pbase = (r0 + rw) * HALO_W + dx;
                #pragma unroll
                for (int mb = 0; mb < 2; mb++) {
                    const int p = pbase + mb * 16 + lm;
                    ldmx4(Ah[rw][mb], smb + A_OFF + a_byte(p, kb * 2 + ksel));
                }
            }
            #pragma unroll
            for (int dy = 0; dy < 3; dy++) {
                const int tap = dy * 3 + dx;
                #pragma unroll
                for (int np = 0; np < 2; np++) {
                    uint32_t Bh[4];
                    ldmx4t(Bh, smb + WH_OFF + tap * 2048 + w_byte(krow, np * 2 + ksel));
                    #pragma unroll
                    for (int rr = 0; rr < 2; rr++)
                        #pragma unroll
                        for (int mb = 0; mb < 2; mb++) {
                            mma16816h(acc[rr][mb][np * 2],     Ah[rr + dy][mb], &Bh[0]);
                            mma16816h(acc[rr][mb][np * 2 + 1], Ah[rr + dy][mb], &Bh[2]);
                        }
                }
            }
        }
    }

    // ---- epilogue ----
    const float* bs = (const float*)(sm + BIAS_OFF);
    const float* gs = (const float*)(sm + GATE_OFF);
    const int grp = lane >> 2, tig = lane & 3;

    #pragma unroll
    for (int rr = 0; rr < 2; rr++) {
        const int y = y0 + r0 + rr;
        #pragma unroll
        for (int mb = 0; mb < 2; mb++) {
            #pragma unroll
            for (int half = 0; half < 2; half++) {
                const int xg = x0 + mb * 16 + grp + half * 8;
                #pragma unroll
                for (int nb = 0; nb < 4; nb++) {
                    const int co = nb * 8 + tig * 2;
                    __half2 hv = *reinterpret_cast<__half2*>(&acc[rr][mb][nb][half]);
                    float v0 = __low2float(hv);
                    float v1 = __high2float(hv);
                    float t0 = fmaxf((v0 + bs[co])     * gs[co],     0.0f);
                    float t1 = fmaxf((v1 + bs[co + 1]) * gs[co + 1], 0.0f);
                    if (SECOND) {
                        size_t i0 = (((size_t)b * Cch + co)     * Himg + y) * Wimg + xg;
                        size_t i1 = (((size_t)b * Cch + co + 1) * Himg + y) * Wimg + xg;
                        out[i0] = t0 + x[i0];
                        out[i1] = t1 + x[i1];
                    } else {
                        __half h0 = __float2half(t0);
                        __half h1 = __float2half(t1);
                        uint32_t uh = (uint32_t)__half_as_ushort(h0)
                                    | ((uint32_t)__half_as_ushort(h1) << 16);
                        size_t pix = (size_t)b * 65536 + y * 256 + xg;
                        g_h[pix * 16 + (co >> 1)] = uh;
                    }
                }
            }
        }
    }
}

extern "C" void kernel_launch(void* const* d_in, const int* in_sizes, int n_in,
                              void* d_out, int out_size)
{
    const float* x    = (const float*)d_in[0];
    const float* gate = (const float*)d_in[1];
    const float* w1   = (const float*)d_in[2];
    const float* b1   = (const float*)d_in[3];
    const float* w2   = (const float*)d_in[4];
    const float* b2   = (const float*)d_in[5];
    float*       out  = (float*)d_out;
    (void)in_sizes; (void)n_in; (void)out_size;

    cudaFuncSetAttribute(conv_hmma<false>,
                         cudaFuncAttributeMaxDynamicSharedMemorySize, SMEM_BYTES);
    cudaFuncSetAttribute(conv_hmma<true>,
                         cudaFuncAttributeMaxDynamicSharedMemorySize, SMEM_BYTES);

    dim3 grid(Wimg / TILE_W, Himg / TILE_H, Bsz);   // 8 x 16 x 16 = 2048 CTAs

    conv_hmma<false><<<grid, THREADS, SMEM_BYTES>>>(x, w1, b1, gate, nullptr);
    conv_hmma<true ><<<grid, THREADS, SMEM_BYTES>>>(x, w2, b2, gate, out);
}